// round 14
// baseline (speedup 1.0000x reference)
#include <cuda_runtime.h>
#include <cuda_fp16.h>
#include <cstdint>

#define BB 1024   // batch
#define DD 512    // latent dim
#define HH 1024   // MLP hidden
#define TT 64     // time points

// ---------------------------------------------------------------------------
// Persistent device state (no allocs allowed).
// ---------------------------------------------------------------------------
__device__ __align__(16) float g_z  [BB * DD];   // current z (fp32)
__device__ __align__(16) float g_acc[BB * DD];   // k1 + 2k2 + 2k3
__device__ __align__(16) __half g_zin[BB * DD];  // stage input (fp16)
__device__ __align__(16) __half g_h  [BB * HH];  // hidden activation (fp16)
__device__ __align__(16) __half g_W1h[DD * HH];
__device__ __align__(16) __half g_W2h[HH * DD];
__device__ unsigned g_f1[16];                     // phase1-done per (group,half)
__device__ unsigned g_f2[16];                     // phase2-done per (group,half)

// ---------------------------------------------------------------------------
// SMEM layout (191488 B -> 1 CTA/SM):
// phase1: A slab [0,66560) 64x520h; B ring 3x18432 at 66560; red at 121856
// phase2: stream 3x35840 at [0,107520); red overlays base after drain
// ---------------------------------------------------------------------------
#define A1S    520
#define A1BYTES 66560
#define B1OFF  66560
#define B1BUF  18432
#define REDOFF 121856
#define A2STR  136
#define ABYTE2 17408
#define BBYTE2 18432
#define BUF2   35840
#define SMEM_TOTAL 191488

// ---------------------------------------------------------------------------
// PTX helpers
// ---------------------------------------------------------------------------
__device__ __forceinline__ void cpa16(void* dst, const void* src) {
    uint32_t d = (uint32_t)__cvta_generic_to_shared(dst);
    asm volatile("cp.async.cg.shared.global [%0], [%1], 16;\n" :: "r"(d), "l"(src));
}
__device__ __forceinline__ void cp_commit() {
    asm volatile("cp.async.commit_group;\n" ::: "memory");
}
template <int N>
__device__ __forceinline__ void cp_wait() {
    asm volatile("cp.async.wait_group %0;\n" :: "n"(N) : "memory");
}
__device__ __forceinline__ void ldsm4(uint32_t* r, const __half* p) {
    uint32_t a = (uint32_t)__cvta_generic_to_shared(p);
    asm volatile("ldmatrix.sync.aligned.m8n8.x4.shared.b16 {%0,%1,%2,%3},[%4];\n"
                 : "=r"(r[0]), "=r"(r[1]), "=r"(r[2]), "=r"(r[3]) : "r"(a));
}
__device__ __forceinline__ void ldsm4t(uint32_t* r, const __half* p) {
    uint32_t a = (uint32_t)__cvta_generic_to_shared(p);
    asm volatile("ldmatrix.sync.aligned.m8n8.x4.trans.shared.b16 {%0,%1,%2,%3},[%4];\n"
                 : "=r"(r[0]), "=r"(r[1]), "=r"(r[2]), "=r"(r[3]) : "r"(a));
}
__device__ __forceinline__ void mma_f16(float* c, const uint32_t* a, uint32_t b0, uint32_t b1) {
    asm volatile("mma.sync.aligned.m16n8k16.row.col.f32.f16.f16.f32 "
                 "{%0,%1,%2,%3}, {%4,%5,%6,%7}, {%8,%9}, {%0,%1,%2,%3};\n"
                 : "+f"(c[0]), "+f"(c[1]), "+f"(c[2]), "+f"(c[3])
                 : "r"(a[0]), "r"(a[1]), "r"(a[2]), "r"(a[3]), "r"(b0), "r"(b1));
}
__device__ __forceinline__ float tanh_fast(float x) {
    float y;
    asm("tanh.approx.f32 %0, %1;\n" : "=f"(y) : "f"(x));
    return y;
}

// ===========================================================================
// Persistent group-local solver.
// 128 CTAs = 8 groups x (2 halves x 8 n).  512 threads, KG=4, 1 CTA/SM.
// ===========================================================================
__global__ void __launch_bounds__(512, 1) k_solver(const float* __restrict__ b1,
                                                   const float* __restrict__ b2,
                                                   const float* __restrict__ t,
                                                   float* __restrict__ traj)
{
    extern __shared__ __align__(16) char sm[];

    const int tid  = threadIdx.x;
    const int wid  = tid >> 5;
    const int lane = tid & 31;
    const int kg   = wid >> 2;                   // 4 k-groups
    const int pos  = wid & 3;
    const int wm = (pos & 1) * 32;
    const int wn = (pos >> 1) * 32;
    const int lr  = lane & 15;
    const int lc8 = (lane >> 4) * 8;
    const int er  = lane >> 2, ec = (lane & 3) * 2;

    const int cta = blockIdx.x;
    const int grp = cta >> 4;                    // group 0..7
    const int q   = cta & 15;
    const int hm  = q >> 3;                      // half 0..1
    const int qn  = q & 7;                       // 0..7
    const int mrow = grp * 128 + hm * 64;        // this CTA's 64 batch rows
    const int n1  = qn * 128;                    // phase1 h columns
    const int n2  = qn * 64;                     // phase2 z columns

    unsigned* f1 = &g_f1[grp * 2 + hm];
    unsigned* f2 = &g_f2[grp * 2 + hm];

#pragma unroll 1
    for (int ii = 0; ii < (TT - 1) * 4; ii++) {
        const int step = ii >> 2, stage = ii & 3;

        // ---- gate: zin rows of my half ready (phase2 of prev iter) ----
        if (ii > 0) {
            if (tid == 0)
                while (*((volatile unsigned*)f2) < 8u * (unsigned)ii) __nanosleep(32);
            __syncthreads();
        }

        // ================= PHASE 1: h[mrow:+64, n1:+128] ====================
        __half* sA1 = (__half*)sm;
        // A slab burst: zin[mrow:+64, 0:512], 8 chunks/thread, one group.
#pragma unroll
        for (int j = 0; j < 8; j++) {
            int ca = tid + j * 512;
            int r = ca >> 6, cc = (ca & 63) * 8;
            cpa16(sA1 + r * A1S + cc, g_zin + (size_t)(mrow + r) * DD + cc);
        }
        cp_commit();
        auto loadB1 = [&](int bt, int b) {       // bt: ns=bt>>2, it=bt&3
            const int it = bt & 3, ns = bt >> 2;
            __half* sB = (__half*)(sm + B1OFF + b * B1BUF);
#pragma unroll
            for (int j = 0; j < 2; j++) {
                int cb = tid + j * 512;
                int rb = cb >> 3, nb = (cb & 7) * 8;
                cpa16(sB + rb * 72 + nb,
                      g_W1h + (size_t)(it * 128 + rb) * HH + n1 + ns * 64 + nb);
            }
            cp_commit();
        };
        loadB1(0, 0);
        loadB1(1, 1);
        {
            float c[2][4][4] = {};
#pragma unroll 1
            for (int tt = 0; tt < 8; tt++) {
                if (tt < 7) cp_wait<1>();
                else        cp_wait<0>();
                __syncthreads();
                if (tt + 2 < 8) loadB1(tt + 2, (tt + 2) % 3);
                const int it = tt & 3;
                const __half* sB = (const __half*)(sm + B1OFF + (tt % 3) * B1BUF);
                uint32_t av[2][2][4], bv[2][2][4];
#pragma unroll
                for (int s = 0; s < 2; s++) {
                    const int kb = kg * 32 + s * 16;
#pragma unroll
                    for (int mt = 0; mt < 2; mt++)
                        ldsm4(av[s][mt], sA1 + (wm + mt * 16 + lr) * A1S + it * 128 + kb + lc8);
#pragma unroll
                    for (int g2 = 0; g2 < 2; g2++)
                        ldsm4t(bv[s][g2], sB + (kb + lr) * 72 + wn + g2 * 16 + lc8);
                }
#pragma unroll
                for (int s = 0; s < 2; s++)
#pragma unroll
                    for (int mt = 0; mt < 2; mt++)
#pragma unroll
                        for (int nt = 0; nt < 4; nt++) {
                            const int g2 = nt >> 1, w = (nt & 1) * 2;
                            mma_f16(c[mt][nt], av[s][mt], bv[s][g2][w], bv[s][g2][w + 1]);
                        }

                if (tt == 3 || tt == 7) {        // subtile epilogue (ns = tt>>2)
                    const int ns = tt >> 2;
                    float* red = (float*)(sm + REDOFF) + kg * (64 * 68);
#pragma unroll
                    for (int mt = 0; mt < 2; mt++)
#pragma unroll
                        for (int nt = 0; nt < 4; nt++)
#pragma unroll
                            for (int h = 0; h < 2; h++) {
                                int lm = wm + mt * 16 + er + h * 8;
                                int ln = wn + nt * 8 + ec;
                                *reinterpret_cast<float2*>(&red[lm * 68 + ln]) =
                                    make_float2(c[mt][nt][2 * h], c[mt][nt][2 * h + 1]);
                            }
                    __syncthreads();
                    const float* rp = (const float*)(sm + REDOFF);
#pragma unroll
                    for (int j = 0; j < 4; j++) {
                        int p  = tid + j * 512;
                        int lm = p >> 5, ln = (p & 31) * 2;
                        int off = lm * 68 + ln;
                        float2 r0 = *reinterpret_cast<const float2*>(&rp[off]);
                        float2 r1 = *reinterpret_cast<const float2*>(&rp[4352 + off]);
                        float2 r2 = *reinterpret_cast<const float2*>(&rp[8704 + off]);
                        float2 r3 = *reinterpret_cast<const float2*>(&rp[13056 + off]);
                        int gn = n1 + ns * 64 + ln;
                        float2 bv0 = *reinterpret_cast<const float2*>(&b1[gn]);
                        float v0 = tanh_fast(r0.x + r1.x + r2.x + r3.x + bv0.x);
                        float v1 = tanh_fast(r0.y + r1.y + r2.y + r3.y + bv0.y);
                        *reinterpret_cast<__half2*>(&g_h[(size_t)(mrow + lm) * HH + gn]) =
                            __halves2half2(__float2half(v0), __float2half(v1));
                    }
#pragma unroll
                    for (int mt = 0; mt < 2; mt++)
#pragma unroll
                        for (int nt = 0; nt < 4; nt++)
#pragma unroll
                            for (int qq = 0; qq < 4; qq++) c[mt][nt][qq] = 0.f;
                }
            }
        }
        __threadfence();
        __syncthreads();
        if (tid == 0) atomicAdd(f1, 1u);

        // ---- gate: h rows of my half fully written ----
        if (tid == 0)
            while (*((volatile unsigned*)f1) < 8u * (unsigned)(ii + 1)) __nanosleep(32);
        __syncthreads();

        // ================= PHASE 2: k[mrow:+64, n2:+64], RK4 ================
        auto load2 = [&](int it, int b) {
            const int kk = it * 128;
            __half* sA = (__half*)(sm + b * BUF2);
            __half* sB = (__half*)(sm + b * BUF2 + ABYTE2);
#pragma unroll
            for (int j = 0; j < 2; j++) {
                int ca = tid + j * 512;
                int r = ca >> 4, cc = (ca & 15) * 8;
                cpa16(sA + r * A2STR + cc, g_h + (size_t)(mrow + r) * HH + kk + cc);
                int cb = tid + j * 512;
                int rb = cb >> 3, nb = (cb & 7) * 8;
                cpa16(sB + rb * 72 + nb, g_W2h + (size_t)(kk + rb) * DD + n2 + nb);
            }
            cp_commit();
        };
        load2(0, 0);
        load2(1, 1);
        {
            float c[2][4][4] = {};
#pragma unroll 1
            for (int it = 0; it < 8; it++) {
                if (it < 7) cp_wait<1>();
                else        cp_wait<0>();
                __syncthreads();
                if (it + 2 < 8) load2(it + 2, (it + 2) % 3);
                const __half* sA = (const __half*)(sm + (it % 3) * BUF2);
                const __half* sB = (const __half*)(sm + (it % 3) * BUF2 + ABYTE2);
                uint32_t av[2][2][4], bv[2][2][4];
#pragma unroll
                for (int s = 0; s < 2; s++) {
                    const int kb = kg * 32 + s * 16;
#pragma unroll
                    for (int mt = 0; mt < 2; mt++)
                        ldsm4(av[s][mt], sA + (wm + mt * 16 + lr) * A2STR + kb + lc8);
#pragma unroll
                    for (int g2 = 0; g2 < 2; g2++)
                        ldsm4t(bv[s][g2], sB + (kb + lr) * 72 + wn + g2 * 16 + lc8);
                }
#pragma unroll
                for (int s = 0; s < 2; s++)
#pragma unroll
                    for (int mt = 0; mt < 2; mt++)
#pragma unroll
                        for (int nt = 0; nt < 4; nt++) {
                            const int g2 = nt >> 1, w = (nt & 1) * 2;
                            mma_f16(c[mt][nt], av[s][mt], bv[s][g2][w], bv[s][g2][w + 1]);
                        }
            }
            __syncthreads();                    // drain before red overlay

            float* red = (float*)sm + kg * (64 * 68);
#pragma unroll
            for (int mt = 0; mt < 2; mt++)
#pragma unroll
                for (int nt = 0; nt < 4; nt++)
#pragma unroll
                    for (int h = 0; h < 2; h++) {
                        int lm = wm + mt * 16 + er + h * 8;
                        int ln = wn + nt * 8 + ec;
                        *reinterpret_cast<float2*>(&red[lm * 68 + ln]) =
                            make_float2(c[mt][nt][2 * h], c[mt][nt][2 * h + 1]);
                    }
            __syncthreads();

            const float* rp = (const float*)sm;
            const float dt = t[step + 1] - t[step];
#pragma unroll
            for (int j = 0; j < 4; j++) {
                int p  = tid + j * 512;
                int lm = p >> 5, ln = (p & 31) * 2;
                int off = lm * 68 + ln;
                float2 r0 = *reinterpret_cast<const float2*>(&rp[off]);
                float2 r1 = *reinterpret_cast<const float2*>(&rp[4352 + off]);
                float2 r2 = *reinterpret_cast<const float2*>(&rp[8704 + off]);
                float2 r3 = *reinterpret_cast<const float2*>(&rp[13056 + off]);
                int gn = n2 + ln;
                float2 bv0 = *reinterpret_cast<const float2*>(&b2[gn]);
                float k0 = r0.x + r1.x + r2.x + r3.x + bv0.x;
                float k1 = r0.y + r1.y + r2.y + r3.y + bv0.y;
                int idx = (mrow + lm) * DD + gn;
                float2 zv = *reinterpret_cast<const float2*>(&g_z[idx]);
                float zi0, zi1;
                if (stage == 0) {
                    *reinterpret_cast<float2*>(&g_acc[idx]) = make_float2(k0, k1);
                    zi0 = zv.x + 0.5f * dt * k0;
                    zi1 = zv.y + 0.5f * dt * k1;
                } else if (stage == 1) {
                    float2 a = *reinterpret_cast<const float2*>(&g_acc[idx]);
                    *reinterpret_cast<float2*>(&g_acc[idx]) =
                        make_float2(a.x + 2.f * k0, a.y + 2.f * k1);
                    zi0 = zv.x + 0.5f * dt * k0;
                    zi1 = zv.y + 0.5f * dt * k1;
                } else if (stage == 2) {
                    float2 a = *reinterpret_cast<const float2*>(&g_acc[idx]);
                    *reinterpret_cast<float2*>(&g_acc[idx]) =
                        make_float2(a.x + 2.f * k0, a.y + 2.f * k1);
                    zi0 = zv.x + dt * k0;
                    zi1 = zv.y + dt * k1;
                } else {
                    float2 a = *reinterpret_cast<const float2*>(&g_acc[idx]);
                    zi0 = zv.x + (dt * (1.0f / 6.0f)) * (a.x + k0);
                    zi1 = zv.y + (dt * (1.0f / 6.0f)) * (a.y + k1);
                    *reinterpret_cast<float2*>(&g_z[idx]) = make_float2(zi0, zi1);
                    *reinterpret_cast<float2*>(&traj[(size_t)(step + 1) * BB * DD + idx]) =
                        make_float2(zi0, zi1);
                }
                *reinterpret_cast<__half2*>(&g_zin[idx]) =
                    __halves2half2(__float2half(zi0), __float2half(zi1));
            }
        }
        __threadfence();
        __syncthreads();
        if (tid == 0) atomicAdd(f2, 1u);
    }
}

// ---------------------------------------------------------------------------
// Setup kernels
// ---------------------------------------------------------------------------
__global__ void convert_kernel(const float* __restrict__ src,
                               __half* __restrict__ dst, int n) {
    int i = blockIdx.x * 256 + threadIdx.x;
    if (i < n) dst[i] = __float2half(src[i]);
}

__global__ void init_kernel(const float* __restrict__ z0, float* __restrict__ traj) {
    int i = blockIdx.x * 256 + threadIdx.x;
    if (i < 16) { g_f1[i] = 0; g_f2[i] = 0; }
    if (i < BB * DD) {
        float v = z0[i];
        g_z[i]   = v;
        traj[i]  = v;
        g_zin[i] = __float2half(v);
    }
}

// ---------------------------------------------------------------------------
extern "C" void kernel_launch(void* const* d_in, const int* in_sizes, int n_in,
                              void* d_out, int out_size) {
    const float* z0 = (const float*)d_in[0];
    const float* t  = (const float*)d_in[1];
    const float* W1 = (const float*)d_in[2];
    const float* b1 = (const float*)d_in[3];
    const float* W2 = (const float*)d_in[4];
    const float* b2 = (const float*)d_in[5];
    float* traj = (float*)d_out;

    __half *w1h, *w2h;
    cudaGetSymbolAddress((void**)&w1h, g_W1h);
    cudaGetSymbolAddress((void**)&w2h, g_W2h);

    cudaFuncSetAttribute(k_solver, cudaFuncAttributeMaxDynamicSharedMemorySize, SMEM_TOTAL);

    convert_kernel<<<(DD * HH + 255) / 256, 256>>>(W1, w1h, DD * HH);
    convert_kernel<<<(HH * DD + 255) / 256, 256>>>(W2, w2h, HH * DD);
    init_kernel<<<(BB * DD + 255) / 256, 256>>>(z0, traj);

    k_solver<<<128, 512, SMEM_TOTAL>>>(b1, b2, t, traj);
}

// round 15
// speedup vs baseline: 1.1268x; 1.1268x over previous
#include <cuda_runtime.h>
#include <cuda_fp16.h>
#include <cstdint>

#define BB 1024   // batch
#define DD 512    // latent dim
#define HH 1024   // MLP hidden
#define TT 64     // time points

// ---------------------------------------------------------------------------
// Persistent device state (no allocs allowed).
// ---------------------------------------------------------------------------
__device__ __align__(16) float g_z  [BB * DD];   // current z (fp32)
__device__ __align__(16) float g_acc[BB * DD];   // k1 + 2k2 + 2k3
__device__ __align__(16) __half g_zin[BB * DD];  // stage input (fp16)
__device__ __align__(16) __half g_h  [BB * HH];  // hidden activation (fp16)
__device__ __align__(16) __half g_W1h[DD * HH];
__device__ __align__(16) __half g_W2h[HH * DD];

// reduction tile row stride (fp32), padded => conflict-free
#define RSTR 68

// ---------------------------------------------------------------------------
// PTX helpers
// ---------------------------------------------------------------------------
__device__ __forceinline__ void cpa16(void* dst, const void* src) {
    uint32_t d = (uint32_t)__cvta_generic_to_shared(dst);
    asm volatile("cp.async.cg.shared.global [%0], [%1], 16;\n" :: "r"(d), "l"(src));
}
__device__ __forceinline__ void cp_commit() {
    asm volatile("cp.async.commit_group;\n" ::: "memory");
}
template <int N>
__device__ __forceinline__ void cp_wait() {
    asm volatile("cp.async.wait_group %0;\n" :: "n"(N) : "memory");
}
__device__ __forceinline__ void ldsm4(uint32_t* r, const __half* p) {
    uint32_t a = (uint32_t)__cvta_generic_to_shared(p);
    asm volatile("ldmatrix.sync.aligned.m8n8.x4.shared.b16 {%0,%1,%2,%3},[%4];\n"
                 : "=r"(r[0]), "=r"(r[1]), "=r"(r[2]), "=r"(r[3]) : "r"(a));
}
__device__ __forceinline__ void ldsm4t(uint32_t* r, const __half* p) {
    uint32_t a = (uint32_t)__cvta_generic_to_shared(p);
    asm volatile("ldmatrix.sync.aligned.m8n8.x4.trans.shared.b16 {%0,%1,%2,%3},[%4];\n"
                 : "=r"(r[0]), "=r"(r[1]), "=r"(r[2]), "=r"(r[3]) : "r"(a));
}
__device__ __forceinline__ void mma_f16(float* c, const uint32_t* a, uint32_t b0, uint32_t b1) {
    asm volatile("mma.sync.aligned.m16n8k16.row.col.f32.f16.f16.f32 "
                 "{%0,%1,%2,%3}, {%4,%5,%6,%7}, {%8,%9}, {%0,%1,%2,%3};\n"
                 : "+f"(c[0]), "+f"(c[1]), "+f"(c[2]), "+f"(c[3])
                 : "r"(a[0]), "r"(a[1]), "r"(a[2]), "r"(a[3]), "r"(b0), "r"(b1));
}
__device__ __forceinline__ float tanh_fast(float x) {
    float y;
    asm("tanh.approx.f32 %0, %1;\n" : "=f"(y) : "f"(x));
    return y;
}

// ---------------------------------------------------------------------------
// Mainloop (R7, PDL-split prologue): CTA tile 64x64, KG k-groups x 4
// position-warps (warp tile 32x32).  BK = KG*32.  Threads = KG*128.
// B (weights) is loaded BEFORE cudaGridDependencySynchronize(); A after.
// Group FIFO: B0,B1,A0,A1, then one combined AB group per refill --
// wait<1> at iteration `it` guarantees tiles 0..it fully resident.
// On exit: per-k-group partials in smem red regions (kg * 64*RSTR), synced.
// ---------------------------------------------------------------------------
template <int KDIM, int NDIM, int KG>
__device__ __forceinline__ void mainloop(
    const __half* __restrict__ A, const __half* __restrict__ B,
    int m0, int n0, char* smbase)
{
    constexpr int BK    = KG * 32;
    constexpr int ASTR  = BK + 8;
    constexpr int BSTR  = 72;
    constexpr int ABYTE = 64 * ASTR * 2;
    constexpr int BBYTE = BK * BSTR * 2;
    constexpr int BUF   = ABYTE + BBYTE;
    constexpr int NT    = KDIM / BK;          // 8 for both gemms
    constexpr int NTHR  = KG * 128;

    const int tid  = threadIdx.x;
    const int wid  = tid >> 5;
    const int lane = tid & 31;
    const int kg   = wid >> 2;
    const int pos  = wid & 3;
    const int wm = (pos & 1) * 32;
    const int wn = (pos >> 1) * 32;
    const int lr  = lane & 15;
    const int lc8 = (lane >> 4) * 8;

    float c[2][4][4] = {};

    auto loadB = [&](int it, int b) {
        const int kk = it * BK;
        __half* sB = (__half*)(smbase + b * BUF + ABYTE);
#pragma unroll
        for (int cb = tid; cb < BK * 8; cb += NTHR) {
            int rb = cb >> 3, nb = (cb & 7) * 8;
            cpa16(sB + rb * BSTR + nb, B + (size_t)(kk + rb) * NDIM + n0 + nb);
        }
        cp_commit();
    };
    auto loadA = [&](int it, int b) {
        const int kk = it * BK;
        __half* sA = (__half*)(smbase + b * BUF);
#pragma unroll
        for (int ca = tid; ca < 64 * (BK / 8); ca += NTHR) {
            int r = ca / (BK / 8), cc = (ca % (BK / 8)) * 8;
            cpa16(sA + r * ASTR + cc, A + (size_t)(m0 + r) * KDIM + kk + cc);
        }
        cp_commit();
    };
    auto load_tile = [&](int it, int b) {
        const int kk = it * BK;
        __half* sA = (__half*)(smbase + b * BUF);
        __half* sB = (__half*)(smbase + b * BUF + ABYTE);
#pragma unroll
        for (int ca = tid; ca < 64 * (BK / 8); ca += NTHR) {
            int r = ca / (BK / 8), cc = (ca % (BK / 8)) * 8;
            cpa16(sA + r * ASTR + cc, A + (size_t)(m0 + r) * KDIM + kk + cc);
        }
#pragma unroll
        for (int cb = tid; cb < BK * 8; cb += NTHR) {
            int rb = cb >> 3, nb = (cb & 7) * 8;
            cpa16(sB + rb * BSTR + nb, B + (size_t)(kk + rb) * NDIM + n0 + nb);
        }
        cp_commit();
    };

    auto compute = [&](int b) {
        const __half* sA = (const __half*)(smbase + b * BUF);
        const __half* sB = (const __half*)(smbase + b * BUF + ABYTE);
        uint32_t av[2][2][4], bv[2][2][4];
#pragma unroll
        for (int s = 0; s < 2; s++) {
            const int kb = kg * 32 + s * 16;
#pragma unroll
            for (int mt = 0; mt < 2; mt++)
                ldsm4(av[s][mt], sA + (wm + mt * 16 + lr) * ASTR + kb + lc8);
#pragma unroll
            for (int g = 0; g < 2; g++)
                ldsm4t(bv[s][g], sB + (kb + lr) * BSTR + wn + g * 16 + lc8);
        }
#pragma unroll
        for (int s = 0; s < 2; s++)
#pragma unroll
            for (int mt = 0; mt < 2; mt++)
#pragma unroll
                for (int nt = 0; nt < 4; nt++) {
                    const int g = nt >> 1, w = (nt & 1) * 2;
                    mma_f16(c[mt][nt], av[s][mt], bv[s][g][w], bv[s][g][w + 1]);
                }
    };

    // --- PDL prologue: independent weight tiles first, then sync, then A ---
    loadB(0, 0);
    loadB(1, 1);
    cudaGridDependencySynchronize();
    loadA(0, 0);
    loadA(1, 1);

#pragma unroll 1
    for (int it = 0; it < NT; it++) {
        if (it < NT - 1) cp_wait<1>();    // all but newest group done
        else             cp_wait<0>();    // last tile: full drain
        __syncthreads();                  // buffer (it+2)%3 free for refill
        if (it + 2 < NT) load_tile(it + 2, (it + 2) % 3);
        compute(it % 3);
    }
    __syncthreads();         // tiles dead; smem reusable as reduction buffer

    // Dump this k-group's partials.
    float* red = (float*)smbase + kg * (64 * RSTR);
    const int er = lane >> 2, ec = (lane & 3) * 2;
#pragma unroll
    for (int mt = 0; mt < 2; mt++)
#pragma unroll
        for (int nt = 0; nt < 4; nt++)
#pragma unroll
            for (int h = 0; h < 2; h++) {
                int lm = wm + mt * 16 + er + h * 8;
                int ln = wn + nt * 8 + ec;
                *reinterpret_cast<float2*>(&red[lm * RSTR + ln]) =
                    make_float2(c[mt][nt][2 * h], c[mt][nt][2 * h + 1]);
            }
    __syncthreads();
}

// ---------------------------------------------------------------------------
// GEMM1: h = tanh(zin @ W1 + b1) -> g_h.  64x64, KG=2, 256 thr,
// grid (16, 16) = 256 CTAs, 2 CTAs/SM.  (R7 proven config + PDL.)
// ---------------------------------------------------------------------------
#define SMEM1 (3 * (64 * 72 * 2 + 64 * 72 * 2))        // 55296
__global__ void __launch_bounds__(256, 2) k_gemm1(const float* __restrict__ b1) {
    extern __shared__ __align__(16) char sm[];
    const int m0 = blockIdx.y * 64, n0 = blockIdx.x * 64;
    mainloop<DD, HH, 2>(g_zin, g_W1h, m0, n0, sm);

    // Final pass: 256 threads x 8 float2 pairs over the 64x64 tile.
    const float* red = (const float*)sm;
    constexpr int RSZ = 64 * RSTR;
    const int tid = threadIdx.x;
#pragma unroll
    for (int j = 0; j < 8; j++) {
        int p  = tid + j * 256;
        int lm = p >> 5, ln = (p & 31) * 2;
        int off = lm * RSTR + ln;
        float2 r0 = *reinterpret_cast<const float2*>(&red[off]);
        float2 r1 = *reinterpret_cast<const float2*>(&red[RSZ + off]);
        int gn = n0 + ln;
        float2 bv = *reinterpret_cast<const float2*>(&b1[gn]);
        float v0 = tanh_fast(r0.x + r1.x + bv.x);
        float v1 = tanh_fast(r0.y + r1.y + bv.y);
        *reinterpret_cast<__half2*>(&g_h[(size_t)(m0 + lm) * HH + gn]) =
            __halves2half2(__float2half(v0), __float2half(v1));
    }
    cudaTriggerProgrammaticLaunchCompletion();
}

// ---------------------------------------------------------------------------
// GEMM2 + RK4 combine.  64x64, KG=4, 512 thr, grid (8, 16) = 128 CTAs.
// (R7 proven config + PDL.)
// ---------------------------------------------------------------------------
#define SMEM2 (3 * (64 * 136 * 2 + 128 * 72 * 2))      // 107520
__global__ void __launch_bounds__(512, 1) k_gemm2(const float* __restrict__ b2,
                                                  const float* __restrict__ t,
                                                  int step, int stage,
                                                  float* __restrict__ traj) {
    extern __shared__ __align__(16) char sm[];
    const int m0 = blockIdx.y * 64, n0 = blockIdx.x * 64;
    mainloop<HH, DD, 4>(g_h, g_W2h, m0, n0, sm);

    // Final pass: 512 threads x 4 float2 pairs over the 64x64 tile.
    const float* rp = (const float*)sm;
    constexpr int RSZ = 64 * RSTR;
    const float dt = t[step + 1] - t[step];
    const int tid = threadIdx.x;
#pragma unroll
    for (int j = 0; j < 4; j++) {
        int p  = tid + j * 512;
        int lm = p >> 5, ln = (p & 31) * 2;
        int off = lm * RSTR + ln;
        float2 r0 = *reinterpret_cast<const float2*>(&rp[off]);
        float2 r1 = *reinterpret_cast<const float2*>(&rp[RSZ + off]);
        float2 r2 = *reinterpret_cast<const float2*>(&rp[2 * RSZ + off]);
        float2 r3 = *reinterpret_cast<const float2*>(&rp[3 * RSZ + off]);
        int gn = n0 + ln;
        float2 bv = *reinterpret_cast<const float2*>(&b2[gn]);
        float k0 = r0.x + r1.x + r2.x + r3.x + bv.x;
        float k1 = r0.y + r1.y + r2.y + r3.y + bv.y;
        int idx = (m0 + lm) * DD + gn;
        float2 zv = *reinterpret_cast<const float2*>(&g_z[idx]);
        float zi0, zi1;
        if (stage == 0) {
            *reinterpret_cast<float2*>(&g_acc[idx]) = make_float2(k0, k1);
            zi0 = zv.x + 0.5f * dt * k0;
            zi1 = zv.y + 0.5f * dt * k1;
        } else if (stage == 1) {
            float2 a = *reinterpret_cast<const float2*>(&g_acc[idx]);
            *reinterpret_cast<float2*>(&g_acc[idx]) =
                make_float2(a.x + 2.f * k0, a.y + 2.f * k1);
            zi0 = zv.x + 0.5f * dt * k0;
            zi1 = zv.y + 0.5f * dt * k1;
        } else if (stage == 2) {
            float2 a = *reinterpret_cast<const float2*>(&g_acc[idx]);
            *reinterpret_cast<float2*>(&g_acc[idx]) =
                make_float2(a.x + 2.f * k0, a.y + 2.f * k1);
            zi0 = zv.x + dt * k0;
            zi1 = zv.y + dt * k1;
        } else {
            float2 a = *reinterpret_cast<const float2*>(&g_acc[idx]);
            zi0 = zv.x + (dt * (1.0f / 6.0f)) * (a.x + k0);
            zi1 = zv.y + (dt * (1.0f / 6.0f)) * (a.y + k1);
            *reinterpret_cast<float2*>(&g_z[idx]) = make_float2(zi0, zi1);
            *reinterpret_cast<float2*>(&traj[(size_t)(step + 1) * BB * DD + idx]) =
                make_float2(zi0, zi1);
        }
        *reinterpret_cast<__half2*>(&g_zin[idx]) =
            __halves2half2(__float2half(zi0), __float2half(zi1));
    }
    cudaTriggerProgrammaticLaunchCompletion();
}

// ---------------------------------------------------------------------------
// Setup kernels
// ---------------------------------------------------------------------------
__global__ void convert_kernel(const float* __restrict__ src,
                               __half* __restrict__ dst, int n) {
    int i = blockIdx.x * 256 + threadIdx.x;
    if (i < n) dst[i] = __float2half(src[i]);
}

__global__ void init_kernel(const float* __restrict__ z0, float* __restrict__ traj) {
    int i = blockIdx.x * 256 + threadIdx.x;
    if (i < BB * DD) {
        float v = z0[i];
        g_z[i]   = v;
        traj[i]  = v;
        g_zin[i] = __float2half(v);
    }
}

// ---------------------------------------------------------------------------
extern "C" void kernel_launch(void* const* d_in, const int* in_sizes, int n_in,
                              void* d_out, int out_size) {
    const float* z0 = (const float*)d_in[0];
    const float* t  = (const float*)d_in[1];
    const float* W1 = (const float*)d_in[2];
    const float* b1 = (const float*)d_in[3];
    const float* W2 = (const float*)d_in[4];
    const float* b2 = (const float*)d_in[5];
    float* traj = (float*)d_out;

    __half *w1h, *w2h;
    cudaGetSymbolAddress((void**)&w1h, g_W1h);
    cudaGetSymbolAddress((void**)&w2h, g_W2h);

    cudaFuncSetAttribute(k_gemm1, cudaFuncAttributeMaxDynamicSharedMemorySize, SMEM1);
    cudaFuncSetAttribute(k_gemm2, cudaFuncAttributeMaxDynamicSharedMemorySize, SMEM2);

    convert_kernel<<<(DD * HH + 255) / 256, 256>>>(W1, w1h, DD * HH);
    convert_kernel<<<(HH * DD + 255) / 256, 256>>>(W2, w2h, HH * DD);
    init_kernel<<<(BB * DD + 255) / 256, 256>>>(z0, traj);

    // PDL launch configs
    cudaLaunchAttribute attr[1];
    attr[0].id = cudaLaunchAttributeProgrammaticStreamSerialization;
    attr[0].val.programmaticStreamSerializationAllowed = 1;

    cudaLaunchConfig_t cfg1 = {};
    cfg1.gridDim  = dim3(HH / 64, BB / 64);   // 16 x 16 = 256 CTAs
    cfg1.blockDim = dim3(256);
    cfg1.dynamicSmemBytes = SMEM1;
    cfg1.attrs = attr;
    cfg1.numAttrs = 1;

    cudaLaunchConfig_t cfg2 = {};
    cfg2.gridDim  = dim3(DD / 64, BB / 64);   // 8 x 16 = 128 CTAs
    cfg2.blockDim = dim3(512);
    cfg2.dynamicSmemBytes = SMEM2;
    cfg2.attrs = attr;
    cfg2.numAttrs = 1;

    for (int step = 0; step < TT - 1; step++) {
        for (int s = 0; s < 4; s++) {
            cudaLaunchKernelEx(&cfg1, k_gemm1, b1);
            cudaLaunchKernelEx(&cfg2, k_gemm2, b2, t, step, s, traj);
        }
    }
}